// round 1
// baseline (speedup 1.0000x reference)
#include <cuda_runtime.h>
#include <cstdint>
#include <cmath>

#define D_MODEL 1024
#define N_HEADS 16
#define D_HEAD  64
#define BATCH   4
#define SEQ     1024
#define ROWS    (BATCH * SEQ)        // 4096
#define BH      (BATCH * N_HEADS)    // 64
#define EPS     1e-5f

// ---------------- scratch (device globals: sanctioned, no runtime alloc) ----
__device__ float g_Q[BH * SEQ * D_HEAD];    // [bh][s][d]
__device__ float g_K[BH * SEQ * D_HEAD];
__device__ float g_V[BH * SEQ * D_HEAD];
__device__ float g_ctx[ROWS * D_MODEL];     // concat-head context
__device__ float g_tmp[ROWS * D_MODEL];     // attn_out, later ff_out
__device__ float g_y1[ROWS * D_MODEL];      // post-LN1
__device__ float g_h[ROWS * D_MODEL];       // ff hidden

// ---------------- fused QKV projection ------------------------------------
// grid (16 s-tiles, 64 bh), 256 threads. BM=64 (s), BN=64 (d_head), BK=16.
__global__ __launch_bounds__(256) void qkv_kernel(
    const float* __restrict__ x,
    const float* __restrict__ Wq, const float* __restrict__ bq,
    const float* __restrict__ Wk, const float* __restrict__ bk,
    const float* __restrict__ Wv, const float* __restrict__ bv,
    float* __restrict__ Qo, float* __restrict__ Ko, float* __restrict__ Vo)
{
    const int bh = blockIdx.y;
    const int b  = bh >> 4;
    const int h  = bh & 15;
    const int s0 = blockIdx.x * 64;
    const int tid = threadIdx.x;

    const float* A  = x  + ((size_t)b * SEQ + s0) * D_MODEL;
    const float* Bq = Wq + (size_t)h * D_MODEL * D_HEAD;
    const float* Bk = Wk + (size_t)h * D_MODEL * D_HEAD;
    const float* Bv = Wv + (size_t)h * D_MODEL * D_HEAD;

    __shared__ float Xs[16][64];
    __shared__ float Wqs[16][64], Wks[16][64], Wvs[16][64];

    const int tx = tid & 15, ty = tid >> 4;
    float aq[4][4] = {}, ak[4][4] = {}, av[4][4] = {};

    const int lm = tid >> 2, lk4 = (tid & 3) * 4;   // X loads: 64 rows x 16 k
    const int lkb = tid >> 4, lnb = (tid & 15) * 4; // W loads: 16 k x 64 n

    for (int k0 = 0; k0 < D_MODEL; k0 += 16) {
        __syncthreads();
        {
            float4 v = *(const float4*)(A + (size_t)lm * D_MODEL + k0 + lk4);
            Xs[lk4 + 0][lm] = v.x; Xs[lk4 + 1][lm] = v.y;
            Xs[lk4 + 2][lm] = v.z; Xs[lk4 + 3][lm] = v.w;
        }
        {
            size_t off = (size_t)(k0 + lkb) * D_HEAD + lnb;
            *(float4*)&Wqs[lkb][lnb] = *(const float4*)(Bq + off);
            *(float4*)&Wks[lkb][lnb] = *(const float4*)(Bk + off);
            *(float4*)&Wvs[lkb][lnb] = *(const float4*)(Bv + off);
        }
        __syncthreads();
#pragma unroll
        for (int kk = 0; kk < 16; kk++) {
            float a[4], wq[4], wk[4], wv[4];
#pragma unroll
            for (int i = 0; i < 4; i++) a[i] = Xs[kk][ty * 4 + i];
#pragma unroll
            for (int j = 0; j < 4; j++) {
                wq[j] = Wqs[kk][tx * 4 + j];
                wk[j] = Wks[kk][tx * 4 + j];
                wv[j] = Wvs[kk][tx * 4 + j];
            }
#pragma unroll
            for (int i = 0; i < 4; i++)
#pragma unroll
                for (int j = 0; j < 4; j++) {
                    aq[i][j] += a[i] * wq[j];
                    ak[i][j] += a[i] * wk[j];
                    av[i][j] += a[i] * wv[j];
                }
        }
    }

    const size_t base = ((size_t)bh * SEQ + s0) * D_HEAD;
#pragma unroll
    for (int i = 0; i < 4; i++) {
        const int m = ty * 4 + i;
#pragma unroll
        for (int j = 0; j < 4; j++) {
            const int n = tx * 4 + j;
            Qo[base + (size_t)m * D_HEAD + n] = aq[i][j] + bq[h * D_HEAD + n];
            Ko[base + (size_t)m * D_HEAD + n] = ak[i][j] + bk[h * D_HEAD + n];
            Vo[base + (size_t)m * D_HEAD + n] = av[i][j] + bv[h * D_HEAD + n];
        }
    }
}

// ---------------- flash attention ------------------------------------------
// grid (16 q-tiles, 64 bh), 64 threads: thread = one query row.
__global__ __launch_bounds__(64) void attn_kernel(
    const float* __restrict__ Q, const float* __restrict__ K,
    const float* __restrict__ V, float* __restrict__ ctx)
{
    const int bh  = blockIdx.y;
    const int s0  = blockIdx.x * 64;
    const int tid = threadIdx.x;

    __shared__ float4 Ks[64][16];
    __shared__ float4 Vs[64][16];

    const float4* qp = (const float4*)(Q + ((size_t)bh * SEQ + s0 + tid) * D_HEAD);
    float4 q[16];
    const float sc = 0.125f; // 1/sqrt(64)
#pragma unroll
    for (int i = 0; i < 16; i++) {
        float4 v = qp[i];
        v.x *= sc; v.y *= sc; v.z *= sc; v.w *= sc;
        q[i] = v;
    }
    float4 o[16];
#pragma unroll
    for (int i = 0; i < 16; i++) o[i] = make_float4(0.f, 0.f, 0.f, 0.f);
    float m = -1e30f, l = 0.f;

    for (int t = 0; t < 16; t++) {
        __syncthreads();
        const float4* kp = (const float4*)(K + ((size_t)bh * SEQ + t * 64 + tid) * D_HEAD);
        const float4* vp = (const float4*)(V + ((size_t)bh * SEQ + t * 64 + tid) * D_HEAD);
#pragma unroll
        for (int i = 0; i < 16; i++) { Ks[tid][i] = kp[i]; Vs[tid][i] = vp[i]; }
        __syncthreads();

        float s[64];
        float mt = m;
#pragma unroll
        for (int j = 0; j < 64; j++) {
            float acc = 0.f;
#pragma unroll
            for (int i = 0; i < 16; i++) {
                float4 kk = Ks[j][i];
                acc += q[i].x * kk.x + q[i].y * kk.y + q[i].z * kk.z + q[i].w * kk.w;
            }
            s[j] = acc;
            mt = fmaxf(mt, acc);
        }
        const float alpha = __expf(m - mt);
        m = mt;
        l *= alpha;
#pragma unroll
        for (int i = 0; i < 16; i++) {
            o[i].x *= alpha; o[i].y *= alpha; o[i].z *= alpha; o[i].w *= alpha;
        }
#pragma unroll
        for (int j = 0; j < 64; j++) {
            const float p = __expf(s[j] - m);
            l += p;
#pragma unroll
            for (int i = 0; i < 16; i++) {
                float4 vv = Vs[j][i];
                o[i].x += p * vv.x; o[i].y += p * vv.y;
                o[i].z += p * vv.z; o[i].w += p * vv.w;
            }
        }
    }

    const float inv = 1.f / l;
    const int b = bh >> 4, h = bh & 15;
    float4* out = (float4*)(ctx + ((size_t)(b * SEQ + s0 + tid)) * D_MODEL + h * D_HEAD);
#pragma unroll
    for (int i = 0; i < 16; i++) {
        float4 v = o[i];
        v.x *= inv; v.y *= inv; v.z *= inv; v.w *= inv;
        out[i] = v;
    }
}

// ---------------- generic SGEMM + bias (+ReLU) ------------------------------
// BM=128, BN=64, BK=16, 256 threads, 8x4 per thread.
template <int RELU>
__global__ __launch_bounds__(256) void gemm_bias(
    const float* __restrict__ A, const float* __restrict__ B,
    const float* __restrict__ bias, float* __restrict__ C,
    int M, int N, int K)
{
    __shared__ float As[16][128];
    __shared__ float Bs[16][64];

    const int tid = threadIdx.x;
    const int m0 = blockIdx.y * 128, n0 = blockIdx.x * 64;
    const int tx = tid & 15, ty = tid >> 4;

    float acc[8][4] = {};

    const int lm = tid >> 1, lk8 = (tid & 1) * 8;   // A: 128 rows x 16 k
    const int lkb = tid >> 4, lnb = (tid & 15) * 4; // B: 16 k x 64 n

    for (int k0 = 0; k0 < K; k0 += 16) {
        __syncthreads();
        {
            const float* ap = A + (size_t)(m0 + lm) * K + k0 + lk8;
            float4 a0 = *(const float4*)(ap);
            float4 a1 = *(const float4*)(ap + 4);
            As[lk8 + 0][lm] = a0.x; As[lk8 + 1][lm] = a0.y;
            As[lk8 + 2][lm] = a0.z; As[lk8 + 3][lm] = a0.w;
            As[lk8 + 4][lm] = a1.x; As[lk8 + 5][lm] = a1.y;
            As[lk8 + 6][lm] = a1.z; As[lk8 + 7][lm] = a1.w;
        }
        *(float4*)&Bs[lkb][lnb] = *(const float4*)(B + (size_t)(k0 + lkb) * N + n0 + lnb);
        __syncthreads();
#pragma unroll
        for (int kk = 0; kk < 16; kk++) {
            float4 a0 = *(float4*)&As[kk][ty * 8];
            float4 a1 = *(float4*)&As[kk][ty * 8 + 4];
            float4 bv = *(float4*)&Bs[kk][tx * 4];
            const float ar[8] = {a0.x, a0.y, a0.z, a0.w, a1.x, a1.y, a1.z, a1.w};
            const float br[4] = {bv.x, bv.y, bv.z, bv.w};
#pragma unroll
            for (int i = 0; i < 8; i++)
#pragma unroll
                for (int j = 0; j < 4; j++)
                    acc[i][j] += ar[i] * br[j];
        }
    }

#pragma unroll
    for (int i = 0; i < 8; i++) {
        const int m = m0 + ty * 8 + i;
#pragma unroll
        for (int j = 0; j < 4; j++) {
            const int n = n0 + tx * 4 + j;
            float v = acc[i][j] + bias[n];
            if (RELU) v = fmaxf(v, 0.f);
            C[(size_t)m * N + n] = v;
        }
    }
}

// ---------------- residual + LayerNorm --------------------------------------
// 1 block per row (1024 cols), 256 threads, float4 per thread.
__global__ __launch_bounds__(256) void add_ln_kernel(
    const float* __restrict__ A, const float* __restrict__ Bb,
    const float* __restrict__ g, const float* __restrict__ be,
    float* __restrict__ out)
{
    const int row = blockIdx.x;
    const int tid = threadIdx.x;

    const float4 a = ((const float4*)(A  + (size_t)row * D_MODEL))[tid];
    const float4 b = ((const float4*)(Bb + (size_t)row * D_MODEL))[tid];
    float4 v = make_float4(a.x + b.x, a.y + b.y, a.z + b.z, a.w + b.w);

    float sum = v.x + v.y + v.z + v.w;
    float sq  = v.x * v.x + v.y * v.y + v.z * v.z + v.w * v.w;
#pragma unroll
    for (int off = 16; off > 0; off >>= 1) {
        sum += __shfl_xor_sync(0xFFFFFFFF, sum, off);
        sq  += __shfl_xor_sync(0xFFFFFFFF, sq,  off);
    }
    __shared__ float ssum[8], ssq[8];
    __shared__ float s_mu, s_inv;
    const int wid = tid >> 5, lane = tid & 31;
    if (lane == 0) { ssum[wid] = sum; ssq[wid] = sq; }
    __syncthreads();
    if (tid == 0) {
        float ts = 0.f, tq = 0.f;
#pragma unroll
        for (int i = 0; i < 8; i++) { ts += ssum[i]; tq += ssq[i]; }
        const float mu = ts * (1.f / D_MODEL);
        const float var = tq * (1.f / D_MODEL) - mu * mu;
        s_mu = mu;
        s_inv = rsqrtf(var + EPS);
    }
    __syncthreads();
    const float mu = s_mu, inv = s_inv;

    const float4 gv  = ((const float4*)g)[tid];
    const float4 bev = ((const float4*)be)[tid];
    float4 r;
    r.x = (v.x - mu) * inv * gv.x + bev.x;
    r.y = (v.y - mu) * inv * gv.y + bev.y;
    r.z = (v.z - mu) * inv * gv.z + bev.z;
    r.w = (v.w - mu) * inv * gv.w + bev.w;
    ((float4*)(out + (size_t)row * D_MODEL))[tid] = r;
}

// ---------------- launch -----------------------------------------------------
extern "C" void kernel_launch(void* const* d_in, const int* in_sizes, int n_in,
                              void* d_out, int out_size)
{
    const float* x   = (const float*)d_in[0];
    const float* Wq  = (const float*)d_in[1];
    const float* bq  = (const float*)d_in[2];
    const float* Wk  = (const float*)d_in[3];
    const float* bk  = (const float*)d_in[4];
    const float* Wv  = (const float*)d_in[5];
    const float* bv  = (const float*)d_in[6];
    const float* Wo  = (const float*)d_in[7];
    const float* bo  = (const float*)d_in[8];
    const float* g1  = (const float*)d_in[9];
    const float* be1 = (const float*)d_in[10];
    const float* W1  = (const float*)d_in[11];
    const float* b1  = (const float*)d_in[12];
    const float* W2  = (const float*)d_in[13];
    const float* b2  = (const float*)d_in[14];
    const float* g2  = (const float*)d_in[15];
    const float* be2 = (const float*)d_in[16];
    float* out = (float*)d_out;

    float *Qp, *Kp, *Vp, *ctx, *tmp, *y1, *hh;
    cudaGetSymbolAddress((void**)&Qp,  g_Q);
    cudaGetSymbolAddress((void**)&Kp,  g_K);
    cudaGetSymbolAddress((void**)&Vp,  g_V);
    cudaGetSymbolAddress((void**)&ctx, g_ctx);
    cudaGetSymbolAddress((void**)&tmp, g_tmp);
    cudaGetSymbolAddress((void**)&y1,  g_y1);
    cudaGetSymbolAddress((void**)&hh,  g_h);

    qkv_kernel<<<dim3(SEQ / 64, BH), 256>>>(x, Wq, bq, Wk, bk, Wv, bv, Qp, Kp, Vp);
    attn_kernel<<<dim3(SEQ / 64, BH), 64>>>(Qp, Kp, Vp, ctx);
    gemm_bias<0><<<dim3(D_MODEL / 64, ROWS / 128), 256>>>(ctx, Wo, bo, tmp, ROWS, D_MODEL, D_MODEL);
    add_ln_kernel<<<ROWS, 256>>>(x, tmp, g1, be1, y1);
    gemm_bias<1><<<dim3(D_MODEL / 64, ROWS / 128), 256>>>(y1, W1, b1, hh, ROWS, D_MODEL, D_MODEL);
    gemm_bias<0><<<dim3(D_MODEL / 64, ROWS / 128), 256>>>(hh, W2, b2, tmp, ROWS, D_MODEL, D_MODEL);
    add_ln_kernel<<<ROWS, 256>>>(y1, tmp, g2, be2, out);
}

// round 3
// speedup vs baseline: 1.4322x; 1.4322x over previous
#include <cuda_runtime.h>
#include <cstdint>

#define D_MODEL 1024
#define N_HEADS 16
#define D_HEAD  64
#define BATCH   4
#define SEQ     1024
#define ROWS    (BATCH * SEQ)        // 4096
#define BH      (BATCH * N_HEADS)    // 64
#define QKVN    3072
#define EPS     1e-5f

// ---------------- scratch ----------------------------------------------------
__device__ float g_xr  [ROWS * D_MODEL];        // RN-tf32 rounded x
__device__ float g_qkv [ROWS * QKVN];           // fused QKV output [m][q|k|v]
__device__ float g_Bqkv[QKVN * D_MODEL];        // transposed+rounded QKV weights [n][k]
__device__ float g_Bo  [D_MODEL * D_MODEL];
__device__ float g_B1  [D_MODEL * D_MODEL];
__device__ float g_B2  [D_MODEL * D_MODEL];
__device__ float g_bqkv[QKVN];
__device__ float g_ctx [ROWS * D_MODEL];        // attention out (rounded)
__device__ float g_tmp [ROWS * D_MODEL];
__device__ float g_y1  [ROWS * D_MODEL];        // exact
__device__ float g_y1r [ROWS * D_MODEL];        // rounded
__device__ float g_h   [ROWS * D_MODEL];        // ReLU hidden (rounded)

// ---------------- helpers ----------------------------------------------------
__device__ __forceinline__ uint32_t smem_u32(const void* p) {
    uint32_t a;
    asm("{ .reg .u64 t; cvta.to.shared.u64 t, %1; cvt.u32.u64 %0, t; }" : "=r"(a) : "l"(p));
    return a;
}
__device__ __forceinline__ float rn_tf32(float f) {
    uint32_t u = __float_as_uint(f);
    u = (u + 0xFFFu + ((u >> 13) & 1u)) & 0xFFFFE000u;
    return __uint_as_float(u);
}
__device__ __forceinline__ float4 rn_tf32_4(float4 v) {
    return make_float4(rn_tf32(v.x), rn_tf32(v.y), rn_tf32(v.z), rn_tf32(v.w));
}

__device__ __forceinline__ void cp16(uint32_t dst, const float* src) {
    asm volatile("cp.async.cg.shared.global [%0], [%1], 16;" :: "r"(dst), "l"(src) : "memory");
}
__device__ __forceinline__ void cp_commit() {
    asm volatile("cp.async.commit_group;" ::: "memory");
}
__device__ __forceinline__ void cp_wait1() {
    asm volatile("cp.async.wait_group 1;" ::: "memory");
}

__device__ __forceinline__ void mma_tf32(float* c, const uint32_t* a, const uint32_t* b) {
    asm volatile(
        "mma.sync.aligned.m16n8k8.row.col.f32.tf32.tf32.f32 "
        "{%0,%1,%2,%3}, {%4,%5,%6,%7}, {%8,%9}, {%0,%1,%2,%3};"
        : "+f"(c[0]), "+f"(c[1]), "+f"(c[2]), "+f"(c[3])
        : "r"(a[0]), "r"(a[1]), "r"(a[2]), "r"(a[3]), "r"(b[0]), "r"(b[1]));
}

// ---------------- mma.sync tf32 GEMM ------------------------------------------
// C[m][n] = A[m][k] * Bt[n][k]^T + bias, M rows, K=1024 fixed, tile 128x128x32.
#define GBM 128
#define GBN 128
#define GBK 32
#define GK  1024
#define GNIT (GK / GBK)              // 32
#define PAD_ROW 36                   // floats per smem row (bank-conflict-free)
#define ST_FLOATS (2 * 128 * PAD_ROW)            // 9216 floats per stage
#define GSMEM_TOTAL (3 * ST_FLOATS * 4)          // 110592 bytes

template <int RELU, int ROUND>
__global__ void __launch_bounds__(256, 1) gemm_mma(
    const float* __restrict__ A, const float* __restrict__ Bt,
    const float* __restrict__ bias, float* __restrict__ C, int Nld)
{
    extern __shared__ float sm[];
    const uint32_t sb = smem_u32(sm);
    const int tid = threadIdx.x, wid = tid >> 5, lane = tid & 31;
    const int m0 = blockIdx.y * GBM, n0 = blockIdx.x * GBN;
    const int wM = (wid & 3) * 32, wN = (wid >> 2) * 64;
    const int g = lane >> 2, tq = lane & 3;

    float acc[2][8][4];
#pragma unroll
    for (int t = 0; t < 2; t++)
#pragma unroll
        for (int n = 0; n < 8; n++)
#pragma unroll
            for (int j = 0; j < 4; j++) acc[t][n][j] = 0.f;

    // stage loader: A tile 128x32 + B tile 128x32, 16B chunks, 256 threads
    auto load_stage = [&](int s, int k0) {
        const uint32_t base = sb + (uint32_t)s * ST_FLOATS * 4;
#pragma unroll
        for (int i = 0; i < 4; i++) {           // A: 1024 chunks
            int c = tid + i * 256;
            int r = c >> 3, q = c & 7;
            cp16(base + (uint32_t)(r * PAD_ROW + q * 4) * 4,
                 A + (size_t)(m0 + r) * GK + k0 + q * 4);
        }
#pragma unroll
        for (int i = 0; i < 4; i++) {           // B: 1024 chunks
            int c = tid + i * 256;
            int r = c >> 3, q = c & 7;
            cp16(base + (uint32_t)(128 * PAD_ROW + r * PAD_ROW + q * 4) * 4,
                 Bt + (size_t)(n0 + r) * GK + k0 + q * 4);
        }
    };

    load_stage(0, 0); cp_commit();
    load_stage(1, GBK); cp_commit();
    cp_wait1();
    __syncthreads();

    for (int it = 0; it < GNIT; it++) {
        if (it + 2 < GNIT) load_stage((it + 2) % 3, (it + 2) * GBK);
        cp_commit();

        const float* As = sm + (it % 3) * ST_FLOATS;
        const float* Bs = As + 128 * PAD_ROW;
#pragma unroll
        for (int kk = 0; kk < GBK; kk += 8) {
            uint32_t a[2][4], b[8][2];
#pragma unroll
            for (int t = 0; t < 2; t++) {
                const float* ap = As + (wM + t * 16 + g) * PAD_ROW + kk + tq;
                a[t][0] = *(const uint32_t*)(ap);
                a[t][1] = *(const uint32_t*)(ap + 8 * PAD_ROW);
                a[t][2] = *(const uint32_t*)(ap + 4);
                a[t][3] = *(const uint32_t*)(ap + 8 * PAD_ROW + 4);
            }
#pragma unroll
            for (int n = 0; n < 8; n++) {
                const float* bp = Bs + (wN + n * 8 + g) * PAD_ROW + kk + tq;
                b[n][0] = *(const uint32_t*)(bp);
                b[n][1] = *(const uint32_t*)(bp + 4);
            }
#pragma unroll
            for (int t = 0; t < 2; t++)
#pragma unroll
                for (int n = 0; n < 8; n++)
                    mma_tf32(acc[t][n], a[t], b[n]);
        }
        cp_wait1();
        __syncthreads();
    }

    // epilogue: bias + relu + optional tf32 rounding, float2 stores
#pragma unroll
    for (int t = 0; t < 2; t++) {
        const int r0 = m0 + wM + t * 16 + g;
#pragma unroll
        for (int n = 0; n < 8; n++) {
            const int cc = n0 + wN + n * 8 + 2 * tq;
            const float2 bv = *(const float2*)(bias + cc);
            float v0 = acc[t][n][0] + bv.x;
            float v1 = acc[t][n][1] + bv.y;
            float v2 = acc[t][n][2] + bv.x;
            float v3 = acc[t][n][3] + bv.y;
            if (RELU) {
                v0 = fmaxf(v0, 0.f); v1 = fmaxf(v1, 0.f);
                v2 = fmaxf(v2, 0.f); v3 = fmaxf(v3, 0.f);
            }
            if (ROUND) {
                v0 = rn_tf32(v0); v1 = rn_tf32(v1);
                v2 = rn_tf32(v2); v3 = rn_tf32(v3);
            }
            *(float2*)(C + (size_t)r0 * Nld + cc) = make_float2(v0, v1);
            *(float2*)(C + (size_t)(r0 + 8) * Nld + cc) = make_float2(v2, v3);
        }
    }
}

// ---------------- prep kernels ------------------------------------------------
__global__ __launch_bounds__(256) void round_x_kernel(const float* __restrict__ in,
                                                      float* __restrict__ out) {
    const size_t i = (size_t)blockIdx.x * 256 + threadIdx.x;
    ((float4*)out)[i] = rn_tf32_4(((const float4*)in)[i]);
}

__global__ void pack_bias_kernel(const float* __restrict__ bq, const float* __restrict__ bk,
                                 const float* __restrict__ bv, float* __restrict__ o) {
    const int t = threadIdx.x;
    const float* src = (blockIdx.x == 0) ? bq : (blockIdx.x == 1) ? bk : bv;
    o[blockIdx.x * 1024 + t] = src[t];
}

// out[C][R] = rn_tf32(in[R][C]), per-z matrix
__global__ __launch_bounds__(256) void transpose_rn(const float* __restrict__ in,
                                                    float* __restrict__ out, int R, int C) {
    __shared__ float t[32][33];
    const size_t zoff = (size_t)blockIdx.z * R * C;
    in += zoff; out += zoff;
    const int c0 = blockIdx.x * 32, r0 = blockIdx.y * 32;
    const int tx = threadIdx.x, ty = threadIdx.y;
#pragma unroll
    for (int i = 0; i < 32; i += 8)
        t[ty + i][tx] = in[(size_t)(r0 + ty + i) * C + c0 + tx];
    __syncthreads();
#pragma unroll
    for (int i = 0; i < 32; i += 8)
        out[(size_t)(c0 + ty + i) * R + r0 + tx] = rn_tf32(t[tx][ty + i]);
}

// ---------------- flash attention (SIMT fp32, strided QKV input) --------------
__global__ __launch_bounds__(64) void attn_kernel(const float* __restrict__ qkv,
                                                  float* __restrict__ ctx)
{
    const int bh = blockIdx.y;
    const int b = bh >> 4, h = bh & 15;
    const int s0 = blockIdx.x * 64;
    const int tid = threadIdx.x;

    __shared__ float4 Ks[64][16];
    __shared__ float4 Vs[64][16];

    const float4* qp = (const float4*)(qkv + (size_t)(b * SEQ + s0 + tid) * QKVN + h * 64);
    float4 q[16];
    const float sc = 0.125f;
#pragma unroll
    for (int i = 0; i < 16; i++) {
        float4 v = qp[i];
        v.x *= sc; v.y *= sc; v.z *= sc; v.w *= sc;
        q[i] = v;
    }
    float4 o[16];
#pragma unroll
    for (int i = 0; i < 16; i++) o[i] = make_float4(0.f, 0.f, 0.f, 0.f);
    float m = -1e30f, l = 0.f;

    for (int t = 0; t < 16; t++) {
        __syncthreads();
        const size_t row = (size_t)(b * SEQ + t * 64 + tid) * QKVN + h * 64;
        const float4* kp = (const float4*)(qkv + row + 1024);
        const float4* vp = (const float4*)(qkv + row + 2048);
#pragma unroll
        for (int i = 0; i < 16; i++) { Ks[tid][i] = kp[i]; Vs[tid][i] = vp[i]; }
        __syncthreads();

        float s[64];
        float mt = m;
#pragma unroll
        for (int j = 0; j < 64; j++) {
            float acc = 0.f;
#pragma unroll
            for (int i = 0; i < 16; i++) {
                float4 kk = Ks[j][i];
                acc += q[i].x * kk.x + q[i].y * kk.y + q[i].z * kk.z + q[i].w * kk.w;
            }
            s[j] = acc;
            mt = fmaxf(mt, acc);
        }
        const float alpha = __expf(m - mt);
        m = mt;
        l *= alpha;
#pragma unroll
        for (int i = 0; i < 16; i++) {
            o[i].x *= alpha; o[i].y *= alpha; o[i].z *= alpha; o[i].w *= alpha;
        }
#pragma unroll
        for (int j = 0; j < 64; j++) {
            const float p = __expf(s[j] - m);
            l += p;
#pragma unroll
            for (int i = 0; i < 16; i++) {
                float4 vv = Vs[j][i];
                o[i].x += p * vv.x; o[i].y += p * vv.y;
                o[i].z += p * vv.z; o[i].w += p * vv.w;
            }
        }
    }

    const float inv = 1.f / l;
    float4* out = (float4*)(ctx + (size_t)(b * SEQ + s0 + tid) * D_MODEL + h * D_HEAD);
#pragma unroll
    for (int i = 0; i < 16; i++) {
        float4 v = o[i];
        v.x *= inv; v.y *= inv; v.z *= inv; v.w *= inv;
        out[i] = rn_tf32_4(v);  // rounded: feeds Wo GEMM
    }
}

// ---------------- residual + LayerNorm ---------------------------------------
template <bool DUAL>
__global__ __launch_bounds__(256) void add_ln_kernel(
    const float* __restrict__ A, const float* __restrict__ Bb,
    const float* __restrict__ g, const float* __restrict__ be,
    float* __restrict__ out, float* __restrict__ outr)
{
    const int row = blockIdx.x;
    const int tid = threadIdx.x;

    const float4 a = ((const float4*)(A + (size_t)row * D_MODEL))[tid];
    const float4 b = ((const float4*)(Bb + (size_t)row * D_MODEL))[tid];
    float4 v = make_float4(a.x + b.x, a.y + b.y, a.z + b.z, a.w + b.w);

    float sum = v.x + v.y + v.z + v.w;
    float sq = v.x * v.x + v.y * v.y + v.z * v.z + v.w * v.w;
#pragma unroll
    for (int off = 16; off > 0; off >>= 1) {
        sum += __shfl_xor_sync(0xFFFFFFFF, sum, off);
        sq  += __shfl_xor_sync(0xFFFFFFFF, sq, off);
    }
    __shared__ float ssum[8], ssq[8];
    __shared__ float s_mu, s_inv;
    const int wid = tid >> 5, lane = tid & 31;
    if (lane == 0) { ssum[wid] = sum; ssq[wid] = sq; }
    __syncthreads();
    if (tid == 0) {
        float ts = 0.f, tq2 = 0.f;
#pragma unroll
        for (int i = 0; i < 8; i++) { ts += ssum[i]; tq2 += ssq[i]; }
        const float mu = ts * (1.f / D_MODEL);
        const float var = tq2 * (1.f / D_MODEL) - mu * mu;
        s_mu = mu;
        s_inv = rsqrtf(var + EPS);
    }
    __syncthreads();
    const float mu = s_mu, inv = s_inv;

    const float4 gv = ((const float4*)g)[tid];
    const float4 bev = ((const float4*)be)[tid];
    float4 r;
    r.x = (v.x - mu) * inv * gv.x + bev.x;
    r.y = (v.y - mu) * inv * gv.y + bev.y;
    r.z = (v.z - mu) * inv * gv.z + bev.z;
    r.w = (v.w - mu) * inv * gv.w + bev.w;
    ((float4*)(out + (size_t)row * D_MODEL))[tid] = r;
    if (DUAL)
        ((float4*)(outr + (size_t)row * D_MODEL))[tid] = rn_tf32_4(r);
}

// ---------------- launch ------------------------------------------------------
extern "C" void kernel_launch(void* const* d_in, const int* in_sizes, int n_in,
                              void* d_out, int out_size)
{
    const float* x   = (const float*)d_in[0];
    const float* Wq  = (const float*)d_in[1];
    const float* bq  = (const float*)d_in[2];
    const float* Wk  = (const float*)d_in[3];
    const float* bk  = (const float*)d_in[4];
    const float* Wv  = (const float*)d_in[5];
    const float* bv  = (const float*)d_in[6];
    const float* Wo  = (const float*)d_in[7];
    const float* bo  = (const float*)d_in[8];
    const float* g1  = (const float*)d_in[9];
    const float* be1 = (const float*)d_in[10];
    const float* W1  = (const float*)d_in[11];
    const float* b1  = (const float*)d_in[12];
    const float* W2  = (const float*)d_in[13];
    const float* b2  = (const float*)d_in[14];
    const float* g2  = (const float*)d_in[15];
    const float* be2 = (const float*)d_in[16];
    float* out = (float*)d_out;

    float *xr, *qkv, *Bqkv, *Bo, *B1, *B2, *bqkv, *ctx, *tmp, *y1, *y1r, *hh;
    cudaGetSymbolAddress((void**)&xr,   g_xr);
    cudaGetSymbolAddress((void**)&qkv,  g_qkv);
    cudaGetSymbolAddress((void**)&Bqkv, g_Bqkv);
    cudaGetSymbolAddress((void**)&Bo,   g_Bo);
    cudaGetSymbolAddress((void**)&B1,   g_B1);
    cudaGetSymbolAddress((void**)&B2,   g_B2);
    cudaGetSymbolAddress((void**)&bqkv, g_bqkv);
    cudaGetSymbolAddress((void**)&ctx,  g_ctx);
    cudaGetSymbolAddress((void**)&tmp,  g_tmp);
    cudaGetSymbolAddress((void**)&y1,   g_y1);
    cudaGetSymbolAddress((void**)&y1r,  g_y1r);
    cudaGetSymbolAddress((void**)&hh,   g_h);

    cudaFuncSetAttribute(gemm_mma<0, 0>, cudaFuncAttributeMaxDynamicSharedMemorySize, GSMEM_TOTAL);
    cudaFuncSetAttribute(gemm_mma<1, 1>, cudaFuncAttributeMaxDynamicSharedMemorySize, GSMEM_TOTAL);

    // prep: round x, pack biases, transpose+round all weights into [n][k]
    round_x_kernel<<<ROWS, 256>>>(x, xr);
    pack_bias_kernel<<<3, 1024>>>(bq, bk, bv, bqkv);
    transpose_rn<<<dim3(2, 32, 16), dim3(32, 8)>>>(Wq, Bqkv, 1024, 64);
    transpose_rn<<<dim3(2, 32, 16), dim3(32, 8)>>>(Wk, Bqkv + 1024 * 1024, 1024, 64);
    transpose_rn<<<dim3(2, 32, 16), dim3(32, 8)>>>(Wv, Bqkv + 2048 * 1024, 1024, 64);
    transpose_rn<<<dim3(32, 32, 1), dim3(32, 8)>>>(Wo, Bo, 1024, 1024);
    transpose_rn<<<dim3(32, 32, 1), dim3(32, 8)>>>(W1, B1, 1024, 1024);
    transpose_rn<<<dim3(32, 32, 1), dim3(32, 8)>>>(W2, B2, 1024, 1024);

    // fused QKV: [4096][3072]
    gemm_mma<0, 0><<<dim3(QKVN / GBN, ROWS / GBM), 256, GSMEM_TOTAL>>>(xr, Bqkv, bqkv, qkv, QKVN);
    attn_kernel<<<dim3(SEQ / 64, BH), 64>>>(qkv, ctx);
    gemm_mma<0, 0><<<dim3(D_MODEL / GBN, ROWS / GBM), 256, GSMEM_TOTAL>>>(ctx, Bo, bo, tmp, D_MODEL);
    add_ln_kernel<true><<<ROWS, 256>>>(x, tmp, g1, be1, y1, y1r);
    gemm_mma<1, 1><<<dim3(D_MODEL / GBN, ROWS / GBM), 256, GSMEM_TOTAL>>>(y1r, B1, b1, hh, D_MODEL);
    gemm_mma<0, 0><<<dim3(D_MODEL / GBN, ROWS / GBM), 256, GSMEM_TOTAL>>>(hh, B2, b2, tmp, D_MODEL);
    add_ln_kernel<false><<<ROWS, 256>>>(y1, tmp, g2, be2, out, nullptr);
}

// round 5
// speedup vs baseline: 1.5738x; 1.0988x over previous
#include <cuda_runtime.h>
#include <cuda_fp16.h>
#include <cstdint>

#define D_MODEL 1024
#define N_HEADS 16
#define D_HEAD  64
#define BATCH   4
#define SEQ     1024
#define ROWS    (BATCH * SEQ)        // 4096
#define BH      (BATCH * N_HEADS)    // 64
#define QKVN    3072
#define GK      1024
#define EPS     1e-5f

// ---------------- scratch ----------------------------------------------------
__device__ __align__(16) __half g_xh  [ROWS * D_MODEL];
__device__ __align__(16) __half g_qkv [ROWS * QKVN];
__device__ __align__(16) __half g_Bqkv[QKVN * D_MODEL];
__device__ __align__(16) __half g_Bo  [D_MODEL * D_MODEL];
__device__ __align__(16) __half g_B1  [D_MODEL * D_MODEL];
__device__ __align__(16) __half g_B2  [D_MODEL * D_MODEL];
__device__ __align__(16) __half g_ctx [ROWS * D_MODEL];
__device__ __align__(16) __half g_y1h [ROWS * D_MODEL];
__device__ __align__(16) __half g_hh  [ROWS * D_MODEL];
__device__ __align__(16) float  g_bqkv[QKVN];
__device__ __align__(16) float  g_tmp [ROWS * D_MODEL];
__device__ __align__(16) float  g_y1  [ROWS * D_MODEL];

// ---------------- helpers ----------------------------------------------------
__device__ __forceinline__ uint32_t smem_u32(const void* p) {
    uint32_t a;
    asm("{ .reg .u64 t; cvta.to.shared.u64 t, %1; cvt.u32.u64 %0, t; }" : "=r"(a) : "l"(p));
    return a;
}
#define SWZ(o) ((o) ^ (((o) >> 3) & 0x70))

__device__ __forceinline__ void cp16(uint32_t dst, const void* src) {
    asm volatile("cp.async.cg.shared.global [%0], [%1], 16;" :: "r"(dst), "l"(src) : "memory");
}
__device__ __forceinline__ void cp_commit() {
    asm volatile("cp.async.commit_group;" ::: "memory");
}
__device__ __forceinline__ void cp_wait1() {
    asm volatile("cp.async.wait_group 1;" ::: "memory");
}

__device__ __forceinline__ void ldsm4(uint32_t& r0, uint32_t& r1, uint32_t& r2, uint32_t& r3,
                                      uint32_t a) {
    asm volatile("ldmatrix.sync.aligned.m8n8.x4.shared.b16 {%0,%1,%2,%3}, [%4];"
                 : "=r"(r0), "=r"(r1), "=r"(r2), "=r"(r3) : "r"(a));
}
__device__ __forceinline__ void mma_h(float* c, const uint32_t* a, uint32_t b0, uint32_t b1) {
    asm volatile(
        "mma.sync.aligned.m16n8k16.row.col.f32.f16.f16.f32 "
        "{%0,%1,%2,%3}, {%4,%5,%6,%7}, {%8,%9}, {%0,%1,%2,%3};"
        : "+f"(c[0]), "+f"(c[1]), "+f"(c[2]), "+f"(c[3])
        : "r"(a[0]), "r"(a[1]), "r"(a[2]), "r"(a[3]), "r"(b0), "r"(b1));
}

// ---------------- fp16 GEMM: C[m][n] = A[m][k] * Bt[n][k]^T + bias -----------
// tile 128x128x64, 256 threads (8 warps: 4m x 2n), 3-stage cp.async.
#define STAGE_BYTES 32768                     // A 16KB + B 16KB
#define GSMEM_TOTAL (3 * STAGE_BYTES)         // 98304

template <int RELU, int OUTHALF>
__global__ void __launch_bounds__(256) gemm_h(
    const __half* __restrict__ A, const __half* __restrict__ Bt,
    const float* __restrict__ bias, float* __restrict__ Cf,
    __half* __restrict__ Ch, int Nld)
{
    extern __shared__ char sm[];
    const uint32_t sb = smem_u32(sm);
    const int tid = threadIdx.x, wid = tid >> 5, lane = tid & 31;
    const int m0 = blockIdx.y * 128, n0 = blockIdx.x * 128;
    const int wM = (wid & 3) * 32, wN = (wid >> 2) * 64;

    float acc[2][8][4];
#pragma unroll
    for (int t = 0; t < 2; t++)
#pragma unroll
        for (int n = 0; n < 8; n++)
#pragma unroll
            for (int j = 0; j < 4; j++) acc[t][n][j] = 0.f;

    auto load_stage = [&](int s, int k0) {
        const uint32_t base = sb + (uint32_t)s * STAGE_BYTES;
#pragma unroll
        for (int i = 0; i < 4; i++) {
            int c = tid + i * 256;
            int r = c >> 3, q = c & 7;
            cp16(base + SWZ((uint32_t)(r * 128 + q * 16)),
                 A + (size_t)(m0 + r) * GK + k0 + q * 8);
        }
#pragma unroll
        for (int i = 0; i < 4; i++) {
            int c = tid + i * 256;
            int r = c >> 3, q = c & 7;
            cp16(base + 16384u + SWZ((uint32_t)(r * 128 + q * 16)),
                 Bt + (size_t)(n0 + r) * GK + k0 + q * 8);
        }
    };

    load_stage(0, 0); cp_commit();
    load_stage(1, 64); cp_commit();
    cp_wait1();
    __syncthreads();

    const int lr15 = lane & 15, l16 = (lane & 16) ? 16 : 0;
    const int bR = (lane & 7) + ((lane & 16) ? 8 : 0), b16 = (lane & 8) ? 16 : 0;

    for (int it = 0; it < 16; it++) {
        if (it + 2 < 16) load_stage((it + 2) % 3, (it + 2) * 64);
        cp_commit();

        const uint32_t aB = sb + (uint32_t)(it % 3) * STAGE_BYTES;
        const uint32_t bB = aB + 16384u;
#pragma unroll
        for (int kb = 0; kb < 4; kb++) {
            uint32_t a[2][4];
#pragma unroll
            for (int t = 0; t < 2; t++)
                ldsm4(a[t][0], a[t][1], a[t][2], a[t][3],
                      aB + SWZ((uint32_t)((wM + t * 16 + lr15) * 128 + kb * 32 + l16)));
#pragma unroll
            for (int nn = 0; nn < 4; nn++) {
                uint32_t b0, b1, b2, b3;
                ldsm4(b0, b1, b2, b3,
                      bB + SWZ((uint32_t)((wN + nn * 16 + bR) * 128 + kb * 32 + b16)));
#pragma unroll
                for (int t = 0; t < 2; t++) {
                    mma_h(acc[t][2 * nn],     a[t], b0, b1);
                    mma_h(acc[t][2 * nn + 1], a[t], b2, b3);
                }
            }
        }
        cp_wait1();
        __syncthreads();
    }

    const int tq = lane & 3, g = lane >> 2;
#pragma unroll
    for (int t = 0; t < 2; t++) {
        const int r0 = m0 + wM + t * 16 + g;
#pragma unroll
        for (int n = 0; n < 8; n++) {
            const int cc = n0 + wN + n * 8 + 2 * tq;
            const float2 bv = *(const float2*)(bias + cc);
            float v0 = acc[t][n][0] + bv.x;
            float v1 = acc[t][n][1] + bv.y;
            float v2 = acc[t][n][2] + bv.x;
            float v3 = acc[t][n][3] + bv.y;
            if (RELU) {
                v0 = fmaxf(v0, 0.f); v1 = fmaxf(v1, 0.f);
                v2 = fmaxf(v2, 0.f); v3 = fmaxf(v3, 0.f);
            }
            if (OUTHALF) {
                *(__half2*)(Ch + (size_t)r0 * Nld + cc)       = __floats2half2_rn(v0, v1);
                *(__half2*)(Ch + (size_t)(r0 + 8) * Nld + cc) = __floats2half2_rn(v2, v3);
            } else {
                *(float2*)(Cf + (size_t)r0 * Nld + cc)       = make_float2(v0, v1);
                *(float2*)(Cf + (size_t)(r0 + 8) * Nld + cc) = make_float2(v2, v3);
            }
        }
    }
}

// ---------------- SIMT fp32 flash attention (proven R3 math, fp16 I/O) -------
__global__ __launch_bounds__(64) void attn_simt(const __half* __restrict__ qkv,
                                                __half* __restrict__ ctx)
{
    const int bh = blockIdx.y, b = bh >> 4, h = bh & 15;
    const int s0 = blockIdx.x * 64;
    const int tid = threadIdx.x;

    __shared__ float4 Ks[64][16];
    __shared__ float4 Vs[64][16];

    const __half2* qp = (const __half2*)(qkv + (size_t)(b * SEQ + s0 + tid) * QKVN + h * 64);
    float4 q[16];
    const float sc = 0.125f;
#pragma unroll
    for (int i = 0; i < 16; i++) {
        float2 lo = __half22float2(qp[2 * i]);
        float2 hi = __half22float2(qp[2 * i + 1]);
        q[i] = make_float4(lo.x * sc, lo.y * sc, hi.x * sc, hi.y * sc);
    }
    float4 o[16];
#pragma unroll
    for (int i = 0; i < 16; i++) o[i] = make_float4(0.f, 0.f, 0.f, 0.f);
    float m = -1e30f, l = 0.f;

    for (int t = 0; t < 16; t++) {
        __syncthreads();
        const size_t row = (size_t)(b * SEQ + t * 64 + tid) * QKVN + h * 64;
        const __half2* kp = (const __half2*)(qkv + row + 1024);
        const __half2* vp = (const __half2*)(qkv + row + 2048);
#pragma unroll
        for (int i = 0; i < 16; i++) {
            float2 klo = __half22float2(kp[2 * i]);
            float2 khi = __half22float2(kp[2 * i + 1]);
            Ks[tid][i] = make_float4(klo.x, klo.y, khi.x, khi.y);
            float2 vlo = __half22float2(vp[2 * i]);
            float2 vhi = __half22float2(vp[2 * i + 1]);
            Vs[tid][i] = make_float4(vlo.x, vlo.y, vhi.x, vhi.y);
        }
        __syncthreads();

        float s[64];
        float mt = m;
#pragma unroll
        for (int j = 0; j < 64; j++) {
            float acc = 0.f;
#pragma unroll
            for (int i = 0; i < 16; i++) {
                float4 kk = Ks[j][i];
                acc += q[i].x * kk.x + q[i].y * kk.y + q[i].z * kk.z + q[i].w * kk.w;
            }
            s[j] = acc;
            mt = fmaxf(mt, acc);
        }
        const float alpha = __expf(m - mt);
        m = mt;
        l *= alpha;
#pragma unroll
        for (int i = 0; i < 16; i++) {
            o[i].x *= alpha; o[i].y *= alpha; o[i].z *= alpha; o[i].w *= alpha;
        }
#pragma unroll
        for (int j = 0; j < 64; j++) {
            const float p = __expf(s[j] - m);
            l += p;
#pragma unroll
            for (int i = 0; i < 16; i++) {
                float4 vv = Vs[j][i];
                o[i].x += p * vv.x; o[i].y += p * vv.y;
                o[i].z += p * vv.z; o[i].w += p * vv.w;
            }
        }
    }

    const float inv = 1.f / l;
    __half2* op = (__half2*)(ctx + (size_t)(b * SEQ + s0 + tid) * D_MODEL + h * D_HEAD);
#pragma unroll
    for (int i = 0; i < 16; i++) {
        op[2 * i]     = __floats2half2_rn(o[i].x * inv, o[i].y * inv);
        op[2 * i + 1] = __floats2half2_rn(o[i].z * inv, o[i].w * inv);
    }
}

// ---------------- fused prep --------------------------------------------------
__global__ void prep_kernel(
    const float* __restrict__ x,
    const float* __restrict__ Wq, const float* __restrict__ Wk, const float* __restrict__ Wv,
    const float* __restrict__ Wo, const float* __restrict__ W1, const float* __restrict__ W2,
    const float* __restrict__ bq, const float* __restrict__ bk, const float* __restrict__ bv,
    __half* __restrict__ xh, __half* __restrict__ Bqkv,
    __half* __restrict__ Bo, __half* __restrict__ B1, __half* __restrict__ B2,
    float* __restrict__ bqkv)
{
    const int z = blockIdx.z;
    const int tx = threadIdx.x, ty = threadIdx.y;
    const int tid = ty * 32 + tx;

    if (z == 0) {
        const int c0 = blockIdx.x * 32, r0 = blockIdx.y * 32;
#pragma unroll
        for (int i = 0; i < 32; i += 8)
            xh[(size_t)(r0 + ty + i) * 1024 + c0 + tx] =
                __float2half_rn(x[(size_t)(r0 + ty + i) * 1024 + c0 + tx]);
        if (blockIdx.x == 0 && blockIdx.y == 0) {
            for (int i = tid; i < 3072; i += 256)
                bqkv[i] = (i < 1024) ? bq[i] : (i < 2048) ? bk[i - 1024] : bv[i - 2048];
        }
        return;
    }
    if (blockIdx.y >= 32) return;
    __shared__ float t[32][33];

    if (z <= 3) {
        const float* W = (z == 1) ? Wq : (z == 2) ? Wk : Wv;
        __half* out = Bqkv + (size_t)(z - 1) * 1024 * 1024;
        const int hh = blockIdx.x >> 1, d0 = (blockIdx.x & 1) * 32;
        const int k0 = blockIdx.y * 32;
#pragma unroll
        for (int i = 0; i < 32; i += 8)
            t[ty + i][tx] = W[((size_t)hh * 1024 + k0 + ty + i) * 64 + d0 + tx];
        __syncthreads();
#pragma unroll
        for (int i = 0; i < 32; i += 8)
            out[(size_t)(hh * 64 + d0 + ty + i) * 1024 + k0 + tx] =
                __float2half_rn(t[tx][ty + i]);
    } else {
        const float* W = (z == 4) ? Wo : (z == 5) ? W1 : W2;
        __half* out = (z == 4) ? Bo : (z == 5) ? B1 : B2;
        const int n0 = blockIdx.x * 32, k0 = blockIdx.y * 32;
#pragma unroll
        for (int i = 0; i < 32; i += 8)
            t[ty + i][tx] = W[(size_t)(k0 + ty + i) * 1024 + n0 + tx];
        __syncthreads();
#pragma unroll
        for (int i = 0; i < 32; i += 8)
            out[(size_t)(n0 + ty + i) * 1024 + k0 + tx] = __float2half_rn(t[tx][ty + i]);
    }
}

// ---------------- residual + LayerNorm ---------------------------------------
template <bool DUAL>
__global__ __launch_bounds__(256) void add_ln_kernel(
    const float* __restrict__ A, const float* __restrict__ Bb,
    const float* __restrict__ g, const float* __restrict__ be,
    float* __restrict__ out, __half* __restrict__ outh)
{
    const int row = blockIdx.x;
    const int tid = threadIdx.x;

    const float4 a = ((const float4*)(A + (size_t)row * D_MODEL))[tid];
    const float4 b = ((const float4*)(Bb + (size_t)row * D_MODEL))[tid];
    float4 v = make_float4(a.x + b.x, a.y + b.y, a.z + b.z, a.w + b.w);

    float sum = v.x + v.y + v.z + v.w;
    float sq = v.x * v.x + v.y * v.y + v.z * v.z + v.w * v.w;
#pragma unroll
    for (int off = 16; off > 0; off >>= 1) {
        sum += __shfl_xor_sync(0xFFFFFFFF, sum, off);
        sq  += __shfl_xor_sync(0xFFFFFFFF, sq, off);
    }
    __shared__ float ssum[8], ssq[8];
    __shared__ float s_mu, s_inv;
    const int wid = tid >> 5, lane = tid & 31;
    if (lane == 0) { ssum[wid] = sum; ssq[wid] = sq; }
    __syncthreads();
    if (tid == 0) {
        float ts = 0.f, tq2 = 0.f;
#pragma unroll
        for (int i = 0; i < 8; i++) { ts += ssum[i]; tq2 += ssq[i]; }
        const float mu = ts * (1.f / D_MODEL);
        const float var = tq2 * (1.f / D_MODEL) - mu * mu;
        s_mu = mu;
        s_inv = rsqrtf(var + EPS);
    }
    __syncthreads();
    const float mu = s_mu, inv = s_inv;

    const float4 gv = ((const float4*)g)[tid];
    const float4 bev = ((const float4*)be)[tid];
    float4 r;
    r.x = (v.x - mu) * inv * gv.x + bev.x;
    r.y = (v.y - mu) * inv * gv.y + bev.y;
    r.z = (v.z - mu) * inv * gv.z + bev.z;
    r.w = (v.w - mu) * inv * gv.w + bev.w;
    ((float4*)(out + (size_t)row * D_MODEL))[tid] = r;
    if (DUAL) {
        __half2* op = (__half2*)(outh + (size_t)row * D_MODEL);
        op[2 * tid]     = __floats2half2_rn(r.x, r.y);
        op[2 * tid + 1] = __floats2half2_rn(r.z, r.w);
    }
}

// ---------------- launch ------------------------------------------------------
extern "C" void kernel_launch(void* const* d_in, const int* in_sizes, int n_in,
                              void* d_out, int out_size)
{
    const float* x   = (const float*)d_in[0];
    const float* Wq  = (const float*)d_in[1];
    const float* bq  = (const float*)d_in[2];
    const float* Wk  = (const float*)d_in[3];
    const float* bk  = (const float*)d_in[4];
    const float* Wv  = (const float*)d_in[5];
    const float* bv  = (const float*)d_in[6];
    const float* Wo  = (const float*)d_in[7];
    const float* bo  = (const float*)d_in[8];
    const float* g1  = (const float*)d_in[9];
    const float* be1 = (const float*)d_in[10];
    const float* W1  = (const float*)d_in[11];
    const float* b1  = (const float*)d_in[12];
    const float* W2  = (const float*)d_in[13];
    const float* b2  = (const float*)d_in[14];
    const float* g2  = (const float*)d_in[15];
    const float* be2 = (const float*)d_in[16];
    float* out = (float*)d_out;

    __half *xh, *qkv, *Bqkv, *Bo, *B1, *B2, *ctx, *y1h, *hh;
    float *bqkv, *tmp, *y1;
    cudaGetSymbolAddress((void**)&xh,   g_xh);
    cudaGetSymbolAddress((void**)&qkv,  g_qkv);
    cudaGetSymbolAddress((void**)&Bqkv, g_Bqkv);
    cudaGetSymbolAddress((void**)&Bo,   g_Bo);
    cudaGetSymbolAddress((void**)&B1,   g_B1);
    cudaGetSymbolAddress((void**)&B2,   g_B2);
    cudaGetSymbolAddress((void**)&ctx,  g_ctx);
    cudaGetSymbolAddress((void**)&y1h,  g_y1h);
    cudaGetSymbolAddress((void**)&hh,   g_hh);
    cudaGetSymbolAddress((void**)&bqkv, g_bqkv);
    cudaGetSymbolAddress((void**)&tmp,  g_tmp);
    cudaGetSymbolAddress((void**)&y1,   g_y1);

    cudaFuncSetAttribute(gemm_h<0, 0>, cudaFuncAttributeMaxDynamicSharedMemorySize, GSMEM_TOTAL);
    cudaFuncSetAttribute(gemm_h<0, 1>, cudaFuncAttributeMaxDynamicSharedMemorySize, GSMEM_TOTAL);
    cudaFuncSetAttribute(gemm_h<1, 1>, cudaFuncAttributeMaxDynamicSharedMemorySize, GSMEM_TOTAL);

    // 1. prep
    prep_kernel<<<dim3(32, 128, 7), dim3(32, 8)>>>(x, Wq, Wk, Wv, Wo, W1, W2,
                                                   bq, bk, bv,
                                                   xh, Bqkv, Bo, B1, B2, bqkv);
    // 2. fused QKV (fp16 out)
    gemm_h<0, 1><<<dim3(QKVN / 128, ROWS / 128), 256, GSMEM_TOTAL>>>(
        xh, Bqkv, bqkv, nullptr, qkv, QKVN);
    // 3. attention (proven SIMT fp32 math, fp16 I/O)
    attn_simt<<<dim3(SEQ / 64, BH), 64>>>(qkv, ctx);
    // 4. Wo (fp32 out)
    gemm_h<0, 0><<<dim3(D_MODEL / 128, ROWS / 128), 256, GSMEM_TOTAL>>>(
        ctx, Bo, bo, tmp, nullptr, D_MODEL);
    // 5. LN1 (fp32 + fp16)
    add_ln_kernel<true><<<ROWS, 256>>>(x, tmp, g1, be1, y1, y1h);
    // 6. W1 + ReLU (fp16 out)  <-- ncu captures this launch
    gemm_h<1, 1><<<dim3(D_MODEL / 128, ROWS / 128), 256, GSMEM_TOTAL>>>(
        y1h, B1, b1, nullptr, hh, D_MODEL);
    // 7. W2 (fp32 out)
    gemm_h<0, 0><<<dim3(D_MODEL / 128, ROWS / 128), 256, GSMEM_TOTAL>>>(
        hh, B2, b2, tmp, nullptr, D_MODEL);
    // 8. LN2 -> output
    add_ln_kernel<false><<<ROWS, 256>>>(y1, tmp, g2, be2, out, nullptr);
}

// round 6
// speedup vs baseline: 10.3342x; 6.5665x over previous
#include <cuda_runtime.h>
#include <cuda_fp16.h>
#include <cstdint>

#define D_MODEL 1024
#define N_HEADS 16
#define D_HEAD  64
#define BATCH   4
#define SEQ     1024
#define ROWS    (BATCH * SEQ)        // 4096
#define BH      (BATCH * N_HEADS)    // 64
#define QKVN    3072
#define GK      1024
#define EPS     1e-5f

// ---------------- scratch ----------------------------------------------------
__device__ __align__(16) __half g_xh  [ROWS * D_MODEL];
__device__ __align__(16) __half g_qkv [ROWS * QKVN];
__device__ __align__(16) __half g_vt  [BH * D_HEAD * SEQ];   // V transposed [bh][d][s]
__device__ __align__(16) __half g_Bqkv[QKVN * D_MODEL];
__device__ __align__(16) __half g_Bo  [D_MODEL * D_MODEL];
__device__ __align__(16) __half g_B1  [D_MODEL * D_MODEL];
__device__ __align__(16) __half g_B2  [D_MODEL * D_MODEL];
__device__ __align__(16) __half g_ctx [ROWS * D_MODEL];
__device__ __align__(16) __half g_y1h [ROWS * D_MODEL];
__device__ __align__(16) __half g_hh  [ROWS * D_MODEL];
__device__ __align__(16) float  g_bqkv[QKVN];
__device__ __align__(16) float  g_tmp [ROWS * D_MODEL];
__device__ __align__(16) float  g_y1  [ROWS * D_MODEL];

// ---------------- helpers ----------------------------------------------------
__device__ __forceinline__ uint32_t smem_u32(const void* p) {
    uint32_t a;
    asm("{ .reg .u64 t; cvta.to.shared.u64 t, %1; cvt.u32.u64 %0, t; }" : "=r"(a) : "l"(p));
    return a;
}
#define SWZ(o) ((o) ^ (((o) >> 3) & 0x70))

__device__ __forceinline__ void cp16(uint32_t dst, const void* src) {
    asm volatile("cp.async.cg.shared.global [%0], [%1], 16;" :: "r"(dst), "l"(src) : "memory");
}
__device__ __forceinline__ void cp_commit() {
    asm volatile("cp.async.commit_group;" ::: "memory");
}
__device__ __forceinline__ void cp_wait1() {
    asm volatile("cp.async.wait_group 1;" ::: "memory");
}

__device__ __forceinline__ void ldsm4(uint32_t& r0, uint32_t& r1, uint32_t& r2, uint32_t& r3,
                                      uint32_t a) {
    asm volatile("ldmatrix.sync.aligned.m8n8.x4.shared.b16 {%0,%1,%2,%3}, [%4];"
                 : "=r"(r0), "=r"(r1), "=r"(r2), "=r"(r3) : "r"(a));
}
__device__ __forceinline__ void mma_h(float* c, const uint32_t* a, uint32_t b0, uint32_t b1) {
    asm volatile(
        "mma.sync.aligned.m16n8k16.row.col.f32.f16.f16.f32 "
        "{%0,%1,%2,%3}, {%4,%5,%6,%7}, {%8,%9}, {%0,%1,%2,%3};"
        : "+f"(c[0]), "+f"(c[1]), "+f"(c[2]), "+f"(c[3])
        : "r"(a[0]), "r"(a[1]), "r"(a[2]), "r"(a[3]), "r"(b0), "r"(b1));
}

// ---------------- fp16 GEMM: C[m][n] = A[m][k] * Bt[n][k]^T + bias -----------
// tile 128x128x64, 256 threads (8 warps: 4m x 2n), 3-stage cp.async.
#define STAGE_BYTES 32768
#define GSMEM_TOTAL (3 * STAGE_BYTES)

template <int RELU, int OUTHALF, int VT>
__global__ void __launch_bounds__(256) gemm_h(
    const __half* __restrict__ A, const __half* __restrict__ Bt,
    const float* __restrict__ bias, float* __restrict__ Cf,
    __half* __restrict__ Ch, __half* __restrict__ vt, int Nld)
{
    extern __shared__ char sm[];
    const uint32_t sb = smem_u32(sm);
    const int tid = threadIdx.x, wid = tid >> 5, lane = tid & 31;
    const int m0 = blockIdx.y * 128, n0 = blockIdx.x * 128;
    const int wM = (wid & 3) * 32, wN = (wid >> 2) * 64;

    float acc[2][8][4];
#pragma unroll
    for (int t = 0; t < 2; t++)
#pragma unroll
        for (int n = 0; n < 8; n++)
#pragma unroll
            for (int j = 0; j < 4; j++) acc[t][n][j] = 0.f;

    auto load_stage = [&](int s, int k0) {
        const uint32_t base = sb + (uint32_t)s * STAGE_BYTES;
#pragma unroll
        for (int i = 0; i < 4; i++) {
            int c = tid + i * 256;
            int r = c >> 3, q = c & 7;
            cp16(base + SWZ((uint32_t)(r * 128 + q * 16)),
                 A + (size_t)(m0 + r) * GK + k0 + q * 8);
        }
#pragma unroll
        for (int i = 0; i < 4; i++) {
            int c = tid + i * 256;
            int r = c >> 3, q = c & 7;
            cp16(base + 16384u + SWZ((uint32_t)(r * 128 + q * 16)),
                 Bt + (size_t)(n0 + r) * GK + k0 + q * 8);
        }
    };

    load_stage(0, 0); cp_commit();
    load_stage(1, 64); cp_commit();
    cp_wait1();
    __syncthreads();

    const int lr15 = lane & 15, l16 = (lane & 16) ? 16 : 0;
    const int bR = (lane & 7) + ((lane & 16) ? 8 : 0), b16 = (lane & 8) ? 16 : 0;

    for (int it = 0; it < 16; it++) {
        if (it + 2 < 16) load_stage((it + 2) % 3, (it + 2) * 64);
        cp_commit();

        const uint32_t aB = sb + (uint32_t)(it % 3) * STAGE_BYTES;
        const uint32_t bB = aB + 16384u;
#pragma unroll
        for (int kb = 0; kb < 4; kb++) {
            uint32_t a[2][4];
#pragma unroll
            for (int t = 0; t < 2; t++)
                ldsm4(a[t][0], a[t][1], a[t][2], a[t][3],
                      aB + SWZ((uint32_t)((wM + t * 16 + lr15) * 128 + kb * 32 + l16)));
#pragma unroll
            for (int nn = 0; nn < 4; nn++) {
                uint32_t b0, b1, b2, b3;
                ldsm4(b0, b1, b2, b3,
                      bB + SWZ((uint32_t)((wN + nn * 16 + bR) * 128 + kb * 32 + b16)));
#pragma unroll
                for (int t = 0; t < 2; t++) {
                    mma_h(acc[t][2 * nn],     a[t], b0, b1);
                    mma_h(acc[t][2 * nn + 1], a[t], b2, b3);
                }
            }
        }
        cp_wait1();
        __syncthreads();
    }

    const int tq = lane & 3, g = lane >> 2;
#pragma unroll
    for (int t = 0; t < 2; t++) {
        const int r0 = m0 + wM + t * 16 + g;
#pragma unroll
        for (int n = 0; n < 8; n++) {
            const int cc = n0 + wN + n * 8 + 2 * tq;
            const float2 bv = *(const float2*)(bias + cc);
            float v0 = acc[t][n][0] + bv.x;
            float v1 = acc[t][n][1] + bv.y;
            float v2 = acc[t][n][2] + bv.x;
            float v3 = acc[t][n][3] + bv.y;
            if (RELU) {
                v0 = fmaxf(v0, 0.f); v1 = fmaxf(v1, 0.f);
                v2 = fmaxf(v2, 0.f); v3 = fmaxf(v3, 0.f);
            }
            if (VT && n0 >= 2048) {
                // V region: write transposed vt[bh][d][s]
                const int b = r0 >> 10, s = r0 & 1023;
                const int rel = cc - 2048;
                const int h = rel >> 6, d = rel & 63;
                __half* vp = vt + ((size_t)(b * 16 + h) * 64 + d) * 1024 + s;
                vp[0]        = __float2half_rn(v0);
                vp[1024]     = __float2half_rn(v1);     // d+1
                vp[8]        = __float2half_rn(v2);     // s+8
                vp[1024 + 8] = __float2half_rn(v3);
            } else if (OUTHALF) {
                *(__half2*)(Ch + (size_t)r0 * Nld + cc)       = __floats2half2_rn(v0, v1);
                *(__half2*)(Ch + (size_t)(r0 + 8) * Nld + cc) = __floats2half2_rn(v2, v3);
            } else {
                *(float2*)(Cf + (size_t)r0 * Nld + cc)       = make_float2(v0, v1);
                *(float2*)(Cf + (size_t)(r0 + 8) * Nld + cc) = make_float2(v2, v3);
            }
        }
    }
}

// ---------------- tensor-core flash attention --------------------------------
// 4 warps, 64 q-rows/block; S and PV both use the proven GEMM fragment pattern.
__global__ void __launch_bounds__(128) attn_mma(const __half* __restrict__ qkv,
                                               const __half* __restrict__ vt,
                                               __half* __restrict__ ctx)
{
    __shared__ __align__(16) __half Qs[64 * 64];
    __shared__ __align__(16) __half Ks[2][64 * 64];
    __shared__ __align__(16) __half Vts[2][64 * 64];

    const int bh = blockIdx.y, b = bh >> 4, h = bh & 15;
    const int s0 = blockIdx.x * 64;
    const int tid = threadIdx.x, wid = tid >> 5, lane = tid & 31;
    const uint32_t qB = smem_u32(Qs);
    const uint32_t kB0 = smem_u32(Ks), vB0 = smem_u32(Vts);

#pragma unroll
    for (int i = 0; i < 4; i++) {
        int c = tid + i * 128;
        int r = c >> 3, q = c & 7;
        cp16(qB + SWZ((uint32_t)(r * 128 + q * 16)),
             qkv + (size_t)(b * SEQ + s0 + r) * QKVN + h * 64 + q * 8);
    }
    auto load_kv = [&](int buf, int t) {
#pragma unroll
        for (int i = 0; i < 4; i++) {
            int c = tid + i * 128;
            int r = c >> 3, q = c & 7;
            cp16(kB0 + buf * 8192u + SWZ((uint32_t)(r * 128 + q * 16)),
                 qkv + (size_t)(b * SEQ + t * 64 + r) * QKVN + 1024 + h * 64 + q * 8);
            cp16(vB0 + buf * 8192u + SWZ((uint32_t)(r * 128 + q * 16)),
                 vt + ((size_t)bh * 64 + r) * SEQ + t * 64 + q * 8);
        }
    };
    load_kv(0, 0); cp_commit();
    load_kv(1, 1); cp_commit();
    cp_wait1();
    __syncthreads();

    const int lr15 = lane & 15, l16 = (lane & 16) ? 16 : 0;
    const int bR = (lane & 7) + ((lane & 16) ? 8 : 0), b16 = (lane & 8) ? 16 : 0;

    // Q fragments, scaled by 1/8 (exact in fp16)
    uint32_t aq[4][4];
    const __half2 sc = __floats2half2_rn(0.125f, 0.125f);
#pragma unroll
    for (int kb = 0; kb < 4; kb++) {
        ldsm4(aq[kb][0], aq[kb][1], aq[kb][2], aq[kb][3],
              qB + SWZ((uint32_t)((wid * 16 + lr15) * 128 + kb * 32 + l16)));
#pragma unroll
        for (int j = 0; j < 4; j++) {
            __half2 v = *reinterpret_cast<__half2*>(&aq[kb][j]);
            v = __hmul2(v, sc);
            aq[kb][j] = *reinterpret_cast<uint32_t*>(&v);
        }
    }

    float o[8][4];
#pragma unroll
    for (int j = 0; j < 8; j++)
#pragma unroll
        for (int k = 0; k < 4; k++) o[j][k] = 0.f;
    float mr0 = -1e30f, mr1 = -1e30f, lp0 = 0.f, lp1 = 0.f;

    for (int t = 0; t < 16; t++) {
        const uint32_t kB = kB0 + (t & 1) * 8192u;
        const uint32_t vB = vB0 + (t & 1) * 8192u;

        // S = Q K^T   (A = Q rows, B = K rows [kv][d] — proven pattern)
        float s[8][4];
#pragma unroll
        for (int j = 0; j < 8; j++)
#pragma unroll
            for (int k = 0; k < 4; k++) s[j][k] = 0.f;
#pragma unroll
        for (int kb = 0; kb < 4; kb++) {
#pragma unroll
            for (int nn = 0; nn < 4; nn++) {
                uint32_t b0, b1, b2, b3;
                ldsm4(b0, b1, b2, b3,
                      kB + SWZ((uint32_t)((nn * 16 + bR) * 128 + kb * 32 + b16)));
                mma_h(s[2 * nn],     aq[kb], b0, b1);
                mma_h(s[2 * nn + 1], aq[kb], b2, b3);
            }
        }

        // online softmax (rows g and g+8 of the fragment)
        float mt0 = s[0][0], mt1 = s[0][2];
#pragma unroll
        for (int j = 0; j < 8; j++) {
            mt0 = fmaxf(mt0, fmaxf(s[j][0], s[j][1]));
            mt1 = fmaxf(mt1, fmaxf(s[j][2], s[j][3]));
        }
#pragma unroll
        for (int off = 1; off <= 2; off <<= 1) {
            mt0 = fmaxf(mt0, __shfl_xor_sync(0xFFFFFFFF, mt0, off));
            mt1 = fmaxf(mt1, __shfl_xor_sync(0xFFFFFFFF, mt1, off));
        }
        const float nm0 = fmaxf(mr0, mt0), nm1 = fmaxf(mr1, mt1);
        const float al0 = __expf(mr0 - nm0), al1 = __expf(mr1 - nm1);
        mr0 = nm0; mr1 = nm1;
        float ps0 = 0.f, ps1 = 0.f;
#pragma unroll
        for (int j = 0; j < 8; j++) {
            s[j][0] = __expf(s[j][0] - nm0);
            s[j][1] = __expf(s[j][1] - nm0);
            s[j][2] = __expf(s[j][2] - nm1);
            s[j][3] = __expf(s[j][3] - nm1);
            ps0 += s[j][0] + s[j][1];
            ps1 += s[j][2] + s[j][3];
        }
        lp0 = lp0 * al0 + ps0;
        lp1 = lp1 * al1 + ps1;
#pragma unroll
        for (int j = 0; j < 8; j++) {
            o[j][0] *= al0; o[j][1] *= al0;
            o[j][2] *= al1; o[j][3] *= al1;
        }

        // O += P Vt   (A = P frags from S regs, B = Vt rows [d][kv] — proven pattern)
#pragma unroll
        for (int kb = 0; kb < 4; kb++) {
            uint32_t pa[4];
            __half2 p0 = __floats2half2_rn(s[2 * kb][0], s[2 * kb][1]);
            __half2 p1 = __floats2half2_rn(s[2 * kb][2], s[2 * kb][3]);
            __half2 p2 = __floats2half2_rn(s[2 * kb + 1][0], s[2 * kb + 1][1]);
            __half2 p3 = __floats2half2_rn(s[2 * kb + 1][2], s[2 * kb + 1][3]);
            pa[0] = *reinterpret_cast<uint32_t*>(&p0);
            pa[1] = *reinterpret_cast<uint32_t*>(&p1);
            pa[2] = *reinterpret_cast<uint32_t*>(&p2);
            pa[3] = *reinterpret_cast<uint32_t*>(&p3);
#pragma unroll
            for (int nn = 0; nn < 4; nn++) {
                uint32_t b0, b1, b2, b3;
                ldsm4(b0, b1, b2, b3,
                      vB + SWZ((uint32_t)((nn * 16 + bR) * 128 + kb * 32 + b16)));
                mma_h(o[2 * nn],     pa, b0, b1);
                mma_h(o[2 * nn + 1], pa, b2, b3);
            }
        }

        __syncthreads();
        if (t + 2 < 16) load_kv(t & 1, t + 2);
        cp_commit();
        cp_wait1();
        __syncthreads();
    }

#pragma unroll
    for (int off = 1; off <= 2; off <<= 1) {
        lp0 += __shfl_xor_sync(0xFFFFFFFF, lp0, off);
        lp1 += __shfl_xor_sync(0xFFFFFFFF, lp1, off);
    }
    const float i0 = 1.f / lp0, i1 = 1.f / lp1;
    const int g = lane >> 2, tq = lane & 3;
    const int r0 = b * SEQ + s0 + wid * 16 + g;
#pragma unroll
    for (int j = 0; j < 8; j++) {
        const int cc = h * 64 + 8 * j + 2 * tq;
        *(__half2*)(ctx + (size_t)r0 * D_MODEL + cc) =
            __floats2half2_rn(o[j][0] * i0, o[j][1] * i0);
        *(__half2*)(ctx + (size_t)(r0 + 8) * D_MODEL + cc) =
            __floats2half2_rn(o[j][2] * i1, o[j][3] * i1);
    }
}

// ---------------- prep kernels (split so attn is the 6th launch) --------------
__global__ void prep_x(const float* __restrict__ x, __half* __restrict__ xh) {
    const size_t i = (size_t)blockIdx.x * 256 + threadIdx.x;
    const float4 v = ((const float4*)x)[i];
    __half2* o = (__half2*)xh;
    o[2 * i]     = __floats2half2_rn(v.x, v.y);
    o[2 * i + 1] = __floats2half2_rn(v.z, v.w);
}

__global__ void pack_bias(const float* __restrict__ bq, const float* __restrict__ bk,
                          const float* __restrict__ bv, float* __restrict__ o) {
    const int t = threadIdx.x;
    const float* src = (blockIdx.x == 0) ? bq : (blockIdx.x == 1) ? bk : bv;
    o[blockIdx.x * 1024 + t] = src[t];
}

__global__ void prep_wqkv(const float* __restrict__ Wq, const float* __restrict__ Wk,
                          const float* __restrict__ Wv, __half* __restrict__ Bqkv) {
    __shared__ float t[32][33];
    const int z = blockIdx.z;
    const float* W = (z == 0) ? Wq : (z == 1) ? Wk : Wv;
    __half* out = Bqkv + (size_t)z * 1024 * 1024;
    const int hh = blockIdx.x >> 1, d0 = (blockIdx.x & 1) * 32;
    const int k0 = blockIdx.y * 32;
    const int tx = threadIdx.x, ty = threadIdx.y;
#pragma unroll
    for (int i = 0; i < 32; i += 8)
        t[ty + i][tx] = W[((size_t)hh * 1024 + k0 + ty + i) * 64 + d0 + tx];
    __syncthreads();
#pragma unroll
    for (int i = 0; i < 32; i += 8)
        out[(size_t)(hh * 64 + d0 + ty + i) * 1024 + k0 + tx] = __float2half_rn(t[tx][ty + i]);
}

__global__ void prep_w(const float* __restrict__ Wo, const float* __restrict__ W1,
                       const float* __restrict__ W2,
                       __half* __restrict__ Bo, __half* __restrict__ B1,
                       __half* __restrict__ B2) {
    __shared__ float t[32][33];
    const int z = blockIdx.z;
    const float* W = (z == 0) ? Wo : (z == 1) ? W1 : W2;
    __half* out = (z == 0) ? Bo : (z == 1) ? B1 : B2;
    const int n0 = blockIdx.x * 32, k0 = blockIdx.y * 32;
    const int tx = threadIdx.x, ty = threadIdx.y;
#pragma unroll
    for (int i = 0; i < 32; i += 8)
        t[ty + i][tx] = W[(size_t)(k0 + ty + i) * 1024 + n0 + tx];
    __syncthreads();
#pragma unroll
    for (int i = 0; i < 32; i += 8)
        out[(size_t)(n0 + ty + i) * 1024 + k0 + tx] = __float2half_rn(t[tx][ty + i]);
}

// ---------------- residual + LayerNorm ---------------------------------------
template <bool DUAL>
__global__ __launch_bounds__(256) void add_ln_kernel(
    const float* __restrict__ A, const float* __restrict__ Bb,
    const float* __restrict__ g, const float* __restrict__ be,
    float* __restrict__ out, __half* __restrict__ outh)
{
    const int row = blockIdx.x;
    const int tid = threadIdx.x;

    const float4 a = ((const float4*)(A + (size_t)row * D_MODEL))[tid];
    const float4 b = ((const float4*)(Bb + (size_t)row * D_MODEL))[tid];
    float4 v = make_float4(a.x + b.x, a.y + b.y, a.z + b.z, a.w + b.w);

    float sum = v.x + v.y + v.z + v.w;
    float sq = v.x * v.x + v.y * v.y + v.z * v.z + v.w * v.w;
#pragma unroll
    for (int off = 16; off > 0; off >>= 1) {
        sum += __shfl_xor_sync(0xFFFFFFFF, sum, off);
        sq  += __shfl_xor_sync(0xFFFFFFFF, sq, off);
    }
    __shared__ float ssum[8], ssq[8];
    __shared__ float s_mu, s_inv;
    const int wid = tid >> 5, lane = tid & 31;
    if (lane == 0) { ssum[wid] = sum; ssq[wid] = sq; }
    __syncthreads();
    if (tid == 0) {
        float ts = 0.f, tq2 = 0.f;
#pragma unroll
        for (int i = 0; i < 8; i++) { ts += ssum[i]; tq2 += ssq[i]; }
        const float mu = ts * (1.f / D_MODEL);
        const float var = tq2 * (1.f / D_MODEL) - mu * mu;
        s_mu = mu;
        s_inv = rsqrtf(var + EPS);
    }
    __syncthreads();
    const float mu = s_mu, inv = s_inv;

    const float4 gv = ((const float4*)g)[tid];
    const float4 bev = ((const float4*)be)[tid];
    float4 r;
    r.x = (v.x - mu) * inv * gv.x + bev.x;
    r.y = (v.y - mu) * inv * gv.y + bev.y;
    r.z = (v.z - mu) * inv * gv.z + bev.z;
    r.w = (v.w - mu) * inv * gv.w + bev.w;
    ((float4*)(out + (size_t)row * D_MODEL))[tid] = r;
    if (DUAL) {
        __half2* op = (__half2*)(outh + (size_t)row * D_MODEL);
        op[2 * tid]     = __floats2half2_rn(r.x, r.y);
        op[2 * tid + 1] = __floats2half2_rn(r.z, r.w);
    }
}

// ---------------- launch ------------------------------------------------------
extern "C" void kernel_launch(void* const* d_in, const int* in_sizes, int n_in,
                              void* d_out, int out_size)
{
    const float* x   = (const float*)d_in[0];
    const float* Wq  = (const float*)d_in[1];
    const float* bq  = (const float*)d_in[2];
    const float* Wk  = (const float*)d_in[3];
    const float* bk  = (const float*)d_in[4];
    const float* Wv  = (const float*)d_in[5];
    const float* bv  = (const float*)d_in[6];
    const float* Wo  = (const float*)d_in[7];
    const float* bo  = (const float*)d_in[8];
    const float* g1  = (const float*)d_in[9];
    const float* be1 = (const float*)d_in[10];
    const float* W1  = (const float*)d_in[11];
    const float* b1  = (const float*)d_in[12];
    const float* W2  = (const float*)d_in[13];
    const float* b2  = (const float*)d_in[14];
    const float* g2  = (const float*)d_in[15];
    const float* be2 = (const float*)d_in[16];
    float* out = (float*)d_out;

    __half *xh, *qkv, *vt, *Bqkv, *Bo, *B1, *B2, *ctx, *y1h, *hh;
    float *bqkv, *tmp, *y1;
    cudaGetSymbolAddress((void**)&xh,   g_xh);
    cudaGetSymbolAddress((void**)&qkv,  g_qkv);
    cudaGetSymbolAddress((void**)&vt,   g_vt);
    cudaGetSymbolAddress((void**)&Bqkv, g_Bqkv);
    cudaGetSymbolAddress((void**)&Bo,   g_Bo);
    cudaGetSymbolAddress((void**)&B1,   g_B1);
    cudaGetSymbolAddress((void**)&B2,   g_B2);
    cudaGetSymbolAddress((void**)&ctx,  g_ctx);
    cudaGetSymbolAddress((void**)&y1h,  g_y1h);
    cudaGetSymbolAddress((void**)&hh,   g_hh);
    cudaGetSymbolAddress((void**)&bqkv, g_bqkv);
    cudaGetSymbolAddress((void**)&tmp,  g_tmp);
    cudaGetSymbolAddress((void**)&y1,   g_y1);

    cudaFuncSetAttribute(gemm_h<0, 0, 0>, cudaFuncAttributeMaxDynamicSharedMemorySize, GSMEM_TOTAL);
    cudaFuncSetAttribute(gemm_h<0, 1, 1>, cudaFuncAttributeMaxDynamicSharedMemorySize, GSMEM_TOTAL);
    cudaFuncSetAttribute(gemm_h<1, 1, 0>, cudaFuncAttributeMaxDynamicSharedMemorySize, GSMEM_TOTAL);

    // 1-4: prep (split so attn is launch #6 for ncu)
    prep_x<<<ROWS, 256>>>(x, xh);
    pack_bias<<<3, 1024>>>(bq, bk, bv, bqkv);
    prep_wqkv<<<dim3(32, 32, 3), dim3(32, 8)>>>(Wq, Wk, Wv, Bqkv);
    prep_w<<<dim3(32, 32, 3), dim3(32, 8)>>>(Wo, W1, W2, Bo, B1, B2);
    // 5: fused QKV (Q,K fp16 to qkv; V transposed to vt)
    gemm_h<0, 1, 1><<<dim3(QKVN / 128, ROWS / 128), 256, GSMEM_TOTAL>>>(
        xh, Bqkv, bqkv, nullptr, qkv, vt, QKVN);
    // 6: tensor-core attention   <-- ncu captures this launch
    attn_mma<<<dim3(SEQ / 64, BH), 128>>>(qkv, vt, ctx);
    // 7: Wo (fp32 out)
    gemm_h<0, 0, 0><<<dim3(D_MODEL / 128, ROWS / 128), 256, GSMEM_TOTAL>>>(
        ctx, Bo, bo, tmp, nullptr, nullptr, D_MODEL);
    // 8: LN1
    add_ln_kernel<true><<<ROWS, 256>>>(x, tmp, g1, be1, y1, y1h);
    // 9: W1 + ReLU (fp16 out)
    gemm_h<1, 1, 0><<<dim3(D_MODEL / 128, ROWS / 128), 256, GSMEM_TOTAL>>>(
        y1h, B1, b1, nullptr, hh, nullptr, D_MODEL);
    // 10: W2 (fp32 out)
    gemm_h<0, 0, 0><<<dim3(D_MODEL / 128, ROWS / 128), 256, GSMEM_TOTAL>>>(
        hh, B2, b2, tmp, nullptr, nullptr, D_MODEL);
    // 11: LN2 -> output
    add_ln_kernel<false><<<ROWS, 256>>>(y1, tmp, g2, be2, out, nullptr);
}